// round 1
// baseline (speedup 1.0000x reference)
#include <cuda_runtime.h>

// Problem constants (fixed shapes for this problem instance)
#define BB   8
#define NN   4096
#define EE   16384
#define PP   64
#define DD   256
#define HH   512
#define MSG  256
#define UPD  254
#define STEPS 3

// ---------------- scratch (device globals; no allocations allowed) ----------
__device__ float g_ns[BB * NN * DD];        // node states working copy (33.5 MB)
__device__ float g_h[BB * EE * HH];         // edge hidden / node hidden reuse (268 MB)
__device__ float g_inc[BB * NN * MSG];      // incoming messages (33.5 MB)
__device__ float g_Wn2p[HH * 256];          // W_n2 padded 254 -> 256 cols
__device__ float g_bn2p[256];               // b_n2 padded

// ---------------- small utility kernels -------------------------------------
__global__ void k_copy_ns(const float* __restrict__ src) {
    int i = blockIdx.x * blockDim.x + threadIdx.x;
    if (i < BB * NN * DD) g_ns[i] = src[i];
}
__global__ void k_zero_inc() {
    int i = blockIdx.x * blockDim.x + threadIdx.x;
    if (i < BB * NN * MSG) g_inc[i] = 0.f;
}
__global__ void k_zero_out(float* __restrict__ p, int n) {
    int i = blockIdx.x * blockDim.x + threadIdx.x;
    if (i < n) p[i] = 0.f;
}
__global__ void k_pad_wn2(const float* __restrict__ Wn2, const float* __restrict__ bn2) {
    int i = blockIdx.x * blockDim.x + threadIdx.x;   // 512*256 threads
    if (i < HH * 256) {
        int k = i >> 8, j = i & 255;
        g_Wn2p[i] = (j < UPD) ? Wn2[k * UPD + j] : 0.f;
    }
    if (i < 256) g_bn2p[i] = (i < UPD) ? bn2[i] : 0.f;
}

// ---------------- shared GEMM core: 128x128 tile, BK=16, 256 thr, 8x8 micro --
// As layout: [16][132] (transposed, padded); Bs layout: [16][128]
__device__ __forceinline__ void mm16(const float* __restrict__ As,
                                     const float* __restrict__ Bs,
                                     float acc[8][8], int ty, int tx) {
#pragma unroll
    for (int k = 0; k < 16; ++k) {
        float4 a0 = *(const float4*)(As + k * 132 + ty * 8);
        float4 a1 = *(const float4*)(As + k * 132 + ty * 8 + 4);
        float4 b0 = *(const float4*)(Bs + k * 128 + tx * 8);
        float4 b1 = *(const float4*)(Bs + k * 128 + tx * 8 + 4);
        float av[8] = {a0.x, a0.y, a0.z, a0.w, a1.x, a1.y, a1.z, a1.w};
        float bv[8] = {b0.x, b0.y, b0.z, b0.w, b1.x, b1.y, b1.z, b1.w};
#pragma unroll
        for (int i = 0; i < 8; ++i)
#pragma unroll
            for (int j = 0; j < 8; ++j)
                acc[i][j] = fmaf(av[i], bv[j], acc[i][j]);
    }
}

// Load B tile: 16 (k) x 128 (cols) from row-major W (ldb = row stride)
__device__ __forceinline__ void loadB(float* Bs, const float* __restrict__ W,
                                      int k0, int n0, int ldb, int t) {
#pragma unroll
    for (int i = 0; i < 2; ++i) {
        int f = t + i * 256;
        int k = f >> 5;
        int c = (f & 31) << 2;
        *(float4*)(Bs + k * 128 + c) =
            *(const float4*)(W + (size_t)(k0 + k) * ldb + n0 + c);
    }
}

// Load A tile (plain strided): rows r0..r0+127, cols k0..k0+15
__device__ __forceinline__ void loadA_plain(float* As, const float* __restrict__ A,
                                            int r0, int lda, int k0, int t) {
#pragma unroll
    for (int i = 0; i < 2; ++i) {
        int f = t + i * 256;
        int row = f >> 2;
        int kq = (f & 3) << 2;
        float4 v = *(const float4*)(A + (size_t)(r0 + row) * lda + k0 + kq);
        As[(kq + 0) * 132 + row] = v.x;
        As[(kq + 1) * 132 + row] = v.y;
        As[(kq + 2) * 132 + row] = v.z;
        As[(kq + 3) * 132 + row] = v.w;
    }
}

// Load A tile gathered from g_ns: base[row] is element offset of node row
__device__ __forceinline__ void loadA_gather(float* As, const int* __restrict__ base,
                                             int col0, int t) {
#pragma unroll
    for (int i = 0; i < 2; ++i) {
        int f = t + i * 256;
        int row = f >> 2;
        int kq = (f & 3) << 2;
        float4 v = *(const float4*)(g_ns + base[row] + col0 + kq);
        As[(kq + 0) * 132 + row] = v.x;
        As[(kq + 1) * 132 + row] = v.y;
        As[(kq + 2) * 132 + row] = v.z;
        As[(kq + 3) * 132 + row] = v.w;
    }
}

// ---------------- kernel 1: edge MLP layer 1 (gather + GEMM + bias + relu) ---
// h[r, :] = relu(concat(ns[src], ns[snk]) @ W_e1 + b_e1);  M=B*E, N=512, K=512
__global__ void __launch_bounds__(256)
k_edge1(const float* __restrict__ We1, const float* __restrict__ be1,
        const int* __restrict__ esrc, const int* __restrict__ esnk) {
    __shared__ float As[16 * 132];
    __shared__ float Bs[16 * 128];
    __shared__ int srcb[128], snkb[128];
    int t = threadIdx.x;
    int r0 = blockIdx.y * 128;
    int n0 = blockIdx.x * 128;
    if (t < 128) {
        int r = r0 + t;
        int b = r >> 14;              // / E
        int e = r & (EE - 1);
        srcb[t] = ((b << 12) + esrc[e]) << 8;   // (b*N + src)*256
        snkb[t] = ((b << 12) + esnk[e]) << 8;
    }
    __syncthreads();
    float acc[8][8] = {};
    int ty = t >> 4, tx = t & 15;
    for (int k0 = 0; k0 < 512; k0 += 16) {
        const int* base = (k0 < 256) ? srcb : snkb;
        loadA_gather(As, base, k0 & 255, t);
        loadB(Bs, We1, k0, n0, HH, t);
        __syncthreads();
        mm16(As, Bs, acc, ty, tx);
        __syncthreads();
    }
    float bias[8];
#pragma unroll
    for (int j = 0; j < 8; ++j) bias[j] = be1[n0 + tx * 8 + j];
#pragma unroll
    for (int i = 0; i < 8; ++i) {
        size_t row = r0 + ty * 8 + i;
        float4 v0, v1;
        v0.x = fmaxf(acc[i][0] + bias[0], 0.f);
        v0.y = fmaxf(acc[i][1] + bias[1], 0.f);
        v0.z = fmaxf(acc[i][2] + bias[2], 0.f);
        v0.w = fmaxf(acc[i][3] + bias[3], 0.f);
        v1.x = fmaxf(acc[i][4] + bias[4], 0.f);
        v1.y = fmaxf(acc[i][5] + bias[5], 0.f);
        v1.z = fmaxf(acc[i][6] + bias[6], 0.f);
        v1.w = fmaxf(acc[i][7] + bias[7], 0.f);
        *(float4*)(g_h + row * HH + n0 + tx * 8)     = v0;
        *(float4*)(g_h + row * HH + n0 + tx * 8 + 4) = v1;
    }
}

// ---------------- kernel 2: edge MLP layer 2 + scatter-add -------------------
// msgs = h @ W_e2 + b_e2; incoming[b, snk[e], :] += msgs;  M=B*E, N=256, K=512
__global__ void __launch_bounds__(256)
k_edge2(const float* __restrict__ We2, const float* __restrict__ be2,
        const int* __restrict__ esnk) {
    __shared__ float As[16 * 132];
    __shared__ float Bs[16 * 128];
    __shared__ int snkb[128];
    int t = threadIdx.x;
    int r0 = blockIdx.y * 128;
    int n0 = blockIdx.x * 128;
    if (t < 128) {
        int r = r0 + t;
        int b = r >> 14;
        int e = r & (EE - 1);
        snkb[t] = ((b << 12) + esnk[e]) << 8;   // offset into g_inc
    }
    __syncthreads();
    float acc[8][8] = {};
    int ty = t >> 4, tx = t & 15;
    for (int k0 = 0; k0 < 512; k0 += 16) {
        loadA_plain(As, g_h, r0, HH, k0, t);
        loadB(Bs, We2, k0, n0, MSG, t);
        __syncthreads();
        mm16(As, Bs, acc, ty, tx);
        __syncthreads();
    }
    float bias[8];
#pragma unroll
    for (int j = 0; j < 8; ++j) bias[j] = be2[n0 + tx * 8 + j];
#pragma unroll
    for (int i = 0; i < 8; ++i) {
        int dstb = snkb[ty * 8 + i];
#pragma unroll
        for (int j = 0; j < 8; ++j)
            atomicAdd(&g_inc[dstb + n0 + tx * 8 + j], acc[i][j] + bias[j]);
    }
}

// ---------------- kernel 3: node MLP layer 1 ---------------------------------
// h2 = relu(concat(incoming, ns) @ W_n1 + b_n1);  M=B*N, N=512, K=512
__global__ void __launch_bounds__(256)
k_node1(const float* __restrict__ Wn1, const float* __restrict__ bn1) {
    __shared__ float As[16 * 132];
    __shared__ float Bs[16 * 128];
    int t = threadIdx.x;
    int r0 = blockIdx.y * 128;
    int n0 = blockIdx.x * 128;
    float acc[8][8] = {};
    int ty = t >> 4, tx = t & 15;
    for (int k0 = 0; k0 < 512; k0 += 16) {
        const float* A = (k0 < 256) ? g_inc : g_ns;
        loadA_plain(As, A, r0, DD, k0 & 255, t);
        loadB(Bs, Wn1, k0, n0, HH, t);
        __syncthreads();
        mm16(As, Bs, acc, ty, tx);
        __syncthreads();
    }
    float bias[8];
#pragma unroll
    for (int j = 0; j < 8; ++j) bias[j] = bn1[n0 + tx * 8 + j];
#pragma unroll
    for (int i = 0; i < 8; ++i) {
        size_t row = r0 + ty * 8 + i;
        float4 v0, v1;
        v0.x = fmaxf(acc[i][0] + bias[0], 0.f);
        v0.y = fmaxf(acc[i][1] + bias[1], 0.f);
        v0.z = fmaxf(acc[i][2] + bias[2], 0.f);
        v0.w = fmaxf(acc[i][3] + bias[3], 0.f);
        v1.x = fmaxf(acc[i][4] + bias[4], 0.f);
        v1.y = fmaxf(acc[i][5] + bias[5], 0.f);
        v1.z = fmaxf(acc[i][6] + bias[6], 0.f);
        v1.w = fmaxf(acc[i][7] + bias[7], 0.f);
        *(float4*)(g_h + row * HH + n0 + tx * 8)     = v0;
        *(float4*)(g_h + row * HH + n0 + tx * 8 + 4) = v1;
    }
}

// ---------------- kernel 4: node MLP layer 2 + state update ------------------
// upd = h2 @ W_n2 + b_n2; ns[:, :, 2:256] += upd;  M=B*N, N=256(pad), K=512
__global__ void __launch_bounds__(256)
k_node2() {
    __shared__ float As[16 * 132];
    __shared__ float Bs[16 * 128];
    int t = threadIdx.x;
    int r0 = blockIdx.y * 128;
    int n0 = blockIdx.x * 128;
    float acc[8][8] = {};
    int ty = t >> 4, tx = t & 15;
    for (int k0 = 0; k0 < 512; k0 += 16) {
        loadA_plain(As, g_h, r0, HH, k0, t);
        loadB(Bs, g_Wn2p, k0, n0, 256, t);
        __syncthreads();
        mm16(As, Bs, acc, ty, tx);
        __syncthreads();
    }
#pragma unroll
    for (int i = 0; i < 8; ++i) {
        size_t row = r0 + ty * 8 + i;
#pragma unroll
        for (int j = 0; j < 8; ++j) {
            int jg = n0 + tx * 8 + j;
            if (jg < UPD)
                g_ns[row * DD + 2 + jg] += acc[i][j] + g_bn2p[jg];
        }
    }
}

// ---------------- kernel 5: extraction (batched attn @ ns, split-K) ----------
// out[b,p,d] = sum_n attn[b,p,n] * ns[b,n,d];  per b: 64 x 256 x 4096
// grid: (2 d-tiles, 8 k-splits, 8 batches); BM=64, BN=128, BK=32
__global__ void __launch_bounds__(256)
k_extract(const float* __restrict__ attn, float* __restrict__ out) {
    __shared__ float As[32 * 68];    // [k][row], padded
    __shared__ float Bs[32 * 128];
    int t = threadIdx.x;
    int n0 = blockIdx.x * 128;
    int kbase = blockIdx.y * 512;
    int b = blockIdx.z;
    int ty = t >> 4, tx = t & 15;
    float acc[4][8] = {};
    for (int kt = 0; kt < 16; ++kt) {
        int kabs = kbase + kt * 32;
        // A: attn tile 64 x 32
#pragma unroll
        for (int i = 0; i < 2; ++i) {
            int f = t + i * 256;
            int row = f >> 3;
            int kq = (f & 7) << 2;
            float4 v = *(const float4*)(attn + ((size_t)(b * PP + row)) * NN + kabs + kq);
            As[(kq + 0) * 68 + row] = v.x;
            As[(kq + 1) * 68 + row] = v.y;
            As[(kq + 2) * 68 + row] = v.z;
            As[(kq + 3) * 68 + row] = v.w;
        }
        // B: ns tile 32 x 128
#pragma unroll
        for (int i = 0; i < 4; ++i) {
            int f = t + i * 256;
            int k = f >> 5;
            int c = (f & 31) << 2;
            *(float4*)(Bs + k * 128 + c) =
                *(const float4*)(g_ns + ((size_t)(b * NN + kabs + k)) * DD + n0 + c);
        }
        __syncthreads();
#pragma unroll
        for (int k = 0; k < 32; ++k) {
            float4 a = *(const float4*)(As + k * 68 + ty * 4);
            float4 b0 = *(const float4*)(Bs + k * 128 + tx * 8);
            float4 b1 = *(const float4*)(Bs + k * 128 + tx * 8 + 4);
            float av[4] = {a.x, a.y, a.z, a.w};
            float bv[8] = {b0.x, b0.y, b0.z, b0.w, b1.x, b1.y, b1.z, b1.w};
#pragma unroll
            for (int i = 0; i < 4; ++i)
#pragma unroll
                for (int j = 0; j < 8; ++j)
                    acc[i][j] = fmaf(av[i], bv[j], acc[i][j]);
        }
        __syncthreads();
    }
#pragma unroll
    for (int i = 0; i < 4; ++i)
#pragma unroll
        for (int j = 0; j < 8; ++j)
            atomicAdd(&out[((size_t)(b * PP + ty * 4 + i)) * DD + n0 + tx * 8 + j],
                      acc[i][j]);
}

// ---------------- launcher ---------------------------------------------------
extern "C" void kernel_launch(void* const* d_in, const int* in_sizes, int n_in,
                              void* d_out, int out_size) {
    const float* nodes = (const float*)d_in[0];
    const float* attn  = (const float*)d_in[1];
    const float* We1   = (const float*)d_in[2];
    const float* be1   = (const float*)d_in[3];
    const float* We2   = (const float*)d_in[4];
    const float* be2   = (const float*)d_in[5];
    const float* Wn1   = (const float*)d_in[6];
    const float* bn1   = (const float*)d_in[7];
    const float* Wn2   = (const float*)d_in[8];
    const float* bn2   = (const float*)d_in[9];
    const int*   esrc  = (const int*)d_in[10];
    const int*   esnk  = (const int*)d_in[11];
    float* out = (float*)d_out;

    k_copy_ns<<<(BB * NN * DD + 1023) / 1024, 1024>>>(nodes);
    k_pad_wn2<<<(HH * 256 + 255) / 256, 256>>>(Wn2, bn2);

    for (int s = 0; s < STEPS; ++s) {
        k_zero_inc<<<(BB * NN * MSG + 1023) / 1024, 1024>>>();
        k_edge1<<<dim3(4, (BB * EE) / 128), 256>>>(We1, be1, esrc, esnk);
        k_edge2<<<dim3(2, (BB * EE) / 128), 256>>>(We2, be2, esnk);
        k_node1<<<dim3(4, (BB * NN) / 128), 256>>>(Wn1, bn1);
        k_node2<<<dim3(2, (BB * NN) / 128), 256>>>();
    }

    k_zero_out<<<(out_size + 255) / 256, 256>>>(out, out_size);
    k_extract<<<dim3(2, 8, 8), 256>>>(attn, out);
}

// round 4
// speedup vs baseline: 1.7983x; 1.7983x over previous
#include <cuda_runtime.h>
#include <cuda_bf16.h>
#include <cstdint>

// Problem constants
#define BB   8
#define NN   4096
#define EE   16384
#define PP   64
#define DD   256
#define HH   512
#define MSG  256
#define UPD  254
#define STEPS 3

// ---------------- scratch (device globals) -----------------------------------
__device__ float g_ns[BB * NN * DD];                 // node states fp32 master
__device__ float g_inc[BB * NN * MSG];               // incoming messages (atomics)
__device__ float g_h[(size_t)BB * EE * HH];          // hidden activations fp32
// pre-split, pre-transposed weights: [N][K] bf16, hi + lo
__device__ __nv_bfloat16 g_We1T_hi[HH * HH],  g_We1T_lo[HH * HH];
__device__ __nv_bfloat16 g_We2T_hi[MSG * HH], g_We2T_lo[MSG * HH];
__device__ __nv_bfloat16 g_Wn1T_hi[HH * HH],  g_Wn1T_lo[HH * HH];
__device__ __nv_bfloat16 g_Wn2T_hi[256 * HH], g_Wn2T_lo[256 * HH];  // padded N=256

// ---------------- helpers ------------------------------------------------------
__device__ __forceinline__ uint32_t smem_u32(const void* p) {
    uint32_t a;
    asm("{ .reg .u64 t; cvta.to.shared.u64 t, %1; cvt.u32.u64 %0, t; }" : "=r"(a) : "l"(p));
    return a;
}
__device__ __forceinline__ void ldm4(uint32_t* d, uint32_t addr) {
    asm volatile("ldmatrix.sync.aligned.m8n8.x4.shared.b16 {%0,%1,%2,%3}, [%4];"
        : "=r"(d[0]), "=r"(d[1]), "=r"(d[2]), "=r"(d[3]) : "r"(addr) : "memory");
}
__device__ __forceinline__ void mma_bf16(float* d, const uint32_t* a, uint32_t b0, uint32_t b1) {
    asm volatile("mma.sync.aligned.m16n8k16.row.col.f32.bf16.bf16.f32 "
        "{%0,%1,%2,%3}, {%4,%5,%6,%7}, {%8,%9}, {%0,%1,%2,%3};"
        : "+f"(d[0]), "+f"(d[1]), "+f"(d[2]), "+f"(d[3])
        : "r"(a[0]), "r"(a[1]), "r"(a[2]), "r"(a[3]), "r"(b0), "r"(b1));
}
__device__ __forceinline__ void bsplit(float v, __nv_bfloat16& h, __nv_bfloat16& l) {
    h = __float2bfloat16(v);
    l = __float2bfloat16(v - __bfloat162float(h));
}
__device__ __forceinline__ uint32_t pack2(__nv_bfloat16 a, __nv_bfloat16 b) {
    __nv_bfloat162 t2 = __halves2bfloat162(a, b);
    return *reinterpret_cast<uint32_t*>(&t2);
}

// ---------------- small utility kernels --------------------------------------
__global__ void k_copy_ns(const float* __restrict__ src) {
    int i = blockIdx.x * blockDim.x + threadIdx.x;
    if (i < BB * NN * DD) g_ns[i] = src[i];
}
__global__ void k_zero_inc() {
    int i = blockIdx.x * blockDim.x + threadIdx.x;
    if (i < BB * NN * MSG) g_inc[i] = 0.f;
}
__global__ void k_zero_out(float* __restrict__ p, int n) {
    int i = blockIdx.x * blockDim.x + threadIdx.x;
    if (i < n) p[i] = 0.f;
}
__global__ void k_prep_w(const float* __restrict__ We1, const float* __restrict__ We2,
                         const float* __restrict__ Wn1, const float* __restrict__ Wn2) {
    int i = blockIdx.x * blockDim.x + threadIdx.x;
    const int S1 = HH * HH, S2 = S1 + MSG * HH, S3 = S2 + HH * HH, S4 = S3 + 256 * HH;
    if (i < S1) {
        int n = i >> 9, k = i & 511;
        bsplit(We1[k * HH + n], g_We1T_hi[i], g_We1T_lo[i]);
    } else if (i < S2) {
        int j = i - S1; int n = j >> 9, k = j & 511;
        bsplit(We2[k * MSG + n], g_We2T_hi[j], g_We2T_lo[j]);
    } else if (i < S3) {
        int j = i - S2; int n = j >> 9, k = j & 511;
        bsplit(Wn1[k * HH + n], g_Wn1T_hi[j], g_Wn1T_lo[j]);
    } else if (i < S4) {
        int j = i - S3; int n = j >> 9, k = j & 511;
        float v = (n < UPD) ? Wn2[k * UPD + n] : 0.f;
        bsplit(v, g_Wn2T_hi[j], g_Wn2T_lo[j]);
    }
}

// ---------------- smem tile layout --------------------------------------------
// padded row stride: 40 bf16 = 80 bytes (32 data + 8 pad) -> conflict-free ldmatrix
#define RS 40
#define A_HI 0
#define A_LO 10240
#define B_HI 20480
#define B_LO 30720
#define SM_BYTES 40960

// A tile loader: 128 rows x 32 cols fp32 (row base table) -> split bf16 hi/lo
__device__ __forceinline__ void loadA_f32(char* sm, const float* __restrict__ mat,
                                          const int* __restrict__ rb, int colbase, int t) {
#pragma unroll
    for (int i = 0; i < 4; ++i) {
        int f = t + i * 256;
        int row = f >> 3, seg = f & 7;                 // 8 segs of 4 floats
        float4 v = *(const float4*)(mat + rb[row] + colbase + seg * 4);
        __nv_bfloat16 h0, h1, h2, h3, l0, l1, l2, l3;
        bsplit(v.x, h0, l0); bsplit(v.y, h1, l1);
        bsplit(v.z, h2, l2); bsplit(v.w, h3, l3);
        int off = row * (RS * 2) + seg * 8;            // bytes
        uint2 uh; uh.x = pack2(h0, h1); uh.y = pack2(h2, h3);
        uint2 ul; ul.x = pack2(l0, l1); ul.y = pack2(l2, l3);
        *(uint2*)(sm + A_HI + off) = uh;
        *(uint2*)(sm + A_LO + off) = ul;
    }
}
// B tile loader: 128 n-rows x 32 k from pre-split transposed weights [n][512]
__device__ __forceinline__ void loadB(char* sm,
                                      const __nv_bfloat16* __restrict__ Whi,
                                      const __nv_bfloat16* __restrict__ Wlo,
                                      int n0, int k0, int t) {
#pragma unroll
    for (int i = 0; i < 2; ++i) {
        int f = t + i * 256;
        int row = f >> 2, seg = f & 3;
        size_t src = (size_t)(n0 + row) * HH + k0 + seg * 8;
        int off = row * (RS * 2) + seg * 16;
        *(uint4*)(sm + B_HI + off) = *(const uint4*)(Whi + src);
        *(uint4*)(sm + B_LO + off) = *(const uint4*)(Wlo + src);
    }
}

// ---------------- unified HMMA GEMM kernel ------------------------------------
// MODE 0: edge1  relu(gather(src|snk) @ We1 + b) -> g_h          grid(4,1024)
// MODE 1: edge2  (g_h @ We2 + b) scatter-atomic -> g_inc         grid(2,1024)
// MODE 2: node1  relu([inc|ns] @ Wn1 + b) -> g_h                 grid(4,256)
// MODE 3: node2  g_ns[...,2:256] += (g_h @ Wn2p + b)             grid(2,256)
template<int MODE>
__global__ void __launch_bounds__(256)
k_gemm(const float* __restrict__ bias,
       const int* __restrict__ esrc, const int* __restrict__ esnk) {
    __shared__ char sm[SM_BYTES];
    __shared__ int tab0[128], tab1[128];
    const int t = threadIdx.x, l = t & 31, wid = t >> 5;
    const int wm = wid >> 2, wn = wid & 3;
    const int n0 = blockIdx.x * 128, r0 = blockIdx.y * 128;

    if (t < 128) {
        int r = r0 + t;
        if (MODE == 0) {
            int b = r >> 14, e = r & (EE - 1);
            tab0[t] = ((b << 12) + __ldg(esrc + e)) << 8;
            tab1[t] = ((b << 12) + __ldg(esnk + e)) << 8;
        } else if (MODE == 1) {
            int b = r >> 14, e = r & (EE - 1);
            tab0[t] = r * HH;                               // g_h row base
            tab1[t] = ((b << 12) + __ldg(esnk + e)) << 8;   // scatter dest in g_inc
        } else if (MODE == 2) {
            tab0[t] = r * DD;                               // inc/ns row base (both 256)
        } else {
            tab0[t] = r * HH;
        }
    }
    __syncthreads();

    const __nv_bfloat16 *Whi, *Wlo;
    if (MODE == 0)      { Whi = g_We1T_hi; Wlo = g_We1T_lo; }
    else if (MODE == 1) { Whi = g_We2T_hi; Wlo = g_We2T_lo; }
    else if (MODE == 2) { Whi = g_Wn1T_hi; Wlo = g_Wn1T_lo; }
    else                { Whi = g_Wn2T_hi; Wlo = g_Wn2T_lo; }

    float acc[4][4][4] = {};
    uint32_t smb = smem_u32(sm);
    // ldmatrix per-lane address components
    const int lrow8 = (((l >> 3) & 1) << 3) + (l & 7);
    const int lcol8 = (l >> 4) << 3;

    for (int c = 0; c < 16; ++c) {
        if (MODE == 0) {
            loadA_f32(sm, g_ns, (c < 8) ? tab0 : tab1, (c & 7) * 32, t);
        } else if (MODE == 2) {
            loadA_f32(sm, (c < 8) ? g_inc : g_ns, tab0, (c & 7) * 32, t);
        } else {
            loadA_f32(sm, g_h, tab0, c * 32, t);
        }
        loadB(sm, Whi, Wlo, n0, c * 32, t);
        __syncthreads();
#pragma unroll
        for (int ks = 0; ks < 2; ++ks) {
            uint32_t Af[4][4], Bh[2][4], Bl[2][4];
            const int kcol = ks * 16 + lcol8;
#pragma unroll
            for (int i = 0; i < 4; ++i)
                ldm4(Af[i], smb + A_HI + ((wm * 64 + i * 16 + lrow8) * RS + kcol) * 2);
#pragma unroll
            for (int g = 0; g < 2; ++g) {
                ldm4(Bh[g], smb + B_HI + ((wn * 32 + g * 16 + lrow8) * RS + kcol) * 2);
                ldm4(Bl[g], smb + B_LO + ((wn * 32 + g * 16 + lrow8) * RS + kcol) * 2);
            }
#pragma unroll
            for (int i = 0; i < 4; ++i)
#pragma unroll
                for (int j = 0; j < 4; ++j) {
                    mma_bf16(acc[i][j], Af[i], Bh[j >> 1][j & 1], Bh[j >> 1][(j & 1) + 2]);
                    mma_bf16(acc[i][j], Af[i], Bl[j >> 1][j & 1], Bl[j >> 1][(j & 1) + 2]);
                }
#pragma unroll
            for (int i = 0; i < 4; ++i)
                ldm4(Af[i], smb + A_LO + ((wm * 64 + i * 16 + lrow8) * RS + kcol) * 2);
#pragma unroll
            for (int i = 0; i < 4; ++i)
#pragma unroll
                for (int j = 0; j < 4; ++j)
                    mma_bf16(acc[i][j], Af[i], Bh[j >> 1][j & 1], Bh[j >> 1][(j & 1) + 2]);
        }
        __syncthreads();
    }

    // ---------------- epilogue ----------------
#pragma unroll
    for (int i = 0; i < 4; ++i) {
        const int rl = wm * 64 + i * 16 + (l >> 2);       // local row (upper half)
#pragma unroll
        for (int j = 0; j < 4; ++j) {
            const int c = n0 + wn * 32 + j * 8 + ((l & 3) << 1);
            if (MODE == 0 || MODE == 2) {
                float b0 = __ldg(bias + c), b1 = __ldg(bias + c + 1);
                size_t ro0 = (size_t)(r0 + rl) * HH + c;
                size_t ro1 = (size_t)(r0 + rl + 8) * HH + c;
                float2 v01, v23;
                v01.x = fmaxf(acc[i][j][0] + b0, 0.f);
                v01.y = fmaxf(acc[i][j][1] + b1, 0.f);
                v23.x = fmaxf(acc[i][j][2] + b0, 0.f);
                v23.y = fmaxf(acc[i][j][3] + b1, 0.f);
                *(float2*)(g_h + ro0) = v01;
                *(float2*)(g_h + ro1) = v23;
            } else if (MODE == 1) {
                float b0 = __ldg(bias + c), b1 = __ldg(bias + c + 1);
                int d0 = tab1[rl], d1 = tab1[rl + 8];
                atomicAdd(g_inc + d0 + c,     acc[i][j][0] + b0);
                atomicAdd(g_inc + d0 + c + 1, acc[i][j][1] + b1);
                atomicAdd(g_inc + d1 + c,     acc[i][j][2] + b0);
                atomicAdd(g_inc + d1 + c + 1, acc[i][j][3] + b1);
            } else {
                float b0 = (c < UPD)     ? __ldg(bias + c)     : 0.f;
                float b1 = (c + 1 < UPD) ? __ldg(bias + c + 1) : 0.f;
                size_t ro0 = (size_t)(r0 + rl) * DD + 2;
                size_t ro1 = (size_t)(r0 + rl + 8) * DD + 2;
                if (c < UPD)     g_ns[ro0 + c]     += acc[i][j][0] + b0;
                if (c + 1 < UPD) g_ns[ro0 + c + 1] += acc[i][j][1] + b1;
                if (c < UPD)     g_ns[ro1 + c]     += acc[i][j][2] + b0;
                if (c + 1 < UPD) g_ns[ro1 + c + 1] += acc[i][j][3] + b1;
            }
        }
    }
}

// ---------------- extraction (batched attn @ ns, split-K, SIMT) --------------
__global__ void __launch_bounds__(256)
k_extract(const float* __restrict__ attn, float* __restrict__ out) {
    __shared__ float As[32 * 68];
    __shared__ float Bs[32 * 128];
    int t = threadIdx.x;
    int n0 = blockIdx.x * 128;
    int kbase = blockIdx.y * 512;
    int b = blockIdx.z;
    int ty = t >> 4, tx = t & 15;
    float acc[4][8] = {};
    for (int kt = 0; kt < 16; ++kt) {
        int kabs = kbase + kt * 32;
#pragma unroll
        for (int i = 0; i < 2; ++i) {
            int f = t + i * 256;
            int row = f >> 3;
            int kq = (f & 7) << 2;
            float4 v = *(const float4*)(attn + ((size_t)(b * PP + row)) * NN + kabs + kq);
            As[(kq + 0) * 68 + row] = v.x;
            As[(kq + 1) * 68 + row] = v.y;
            As[(kq + 2) * 68 + row] = v.z;
            As[(kq + 3) * 68 + row] = v.w;
        }
#pragma unroll
        for (int i = 0; i < 4; ++i) {
            int f = t + i * 256;
            int k = f >> 5;
            int c = (f & 31) << 2;
            *(float4*)(Bs + k * 128 + c) =
                *(const float4*)(g_ns + ((size_t)(b * NN + kabs + k)) * DD + n0 + c);
        }
        __syncthreads();
#pragma unroll
        for (int k = 0; k < 32; ++k) {
            float4 a = *(const float4*)(As + k * 68 + ty * 4);
            float4 b0 = *(const float4*)(Bs + k * 128 + tx * 8);
            float4 b1 = *(const float4*)(Bs + k * 128 + tx * 8 + 4);
            float av[4] = {a.x, a.y, a.z, a.w};
            float bv[8] = {b0.x, b0.y, b0.z, b0.w, b1.x, b1.y, b1.z, b1.w};
#pragma unroll
            for (int i = 0; i < 4; ++i)
#pragma unroll
                for (int j = 0; j < 8; ++j)
                    acc[i][j] = fmaf(av[i], bv[j], acc[i][j]);
        }
        __syncthreads();
    }
#pragma unroll
    for (int i = 0; i < 4; ++i)
#pragma unroll
        for (int j = 0; j < 8; ++j)
            atomicAdd(&out[((size_t)(b * PP + ty * 4 + i)) * DD + n0 + tx * 8 + j],
                      acc[i][j]);
}

// ---------------- launcher ----------------------------------------------------
extern "C" void kernel_launch(void* const* d_in, const int* in_sizes, int n_in,
                              void* d_out, int out_size) {
    const float* nodes = (const float*)d_in[0];
    const float* attn  = (const float*)d_in[1];
    const float* We1   = (const float*)d_in[2];
    const float* be1   = (const float*)d_in[3];
    const float* We2   = (const float*)d_in[4];
    const float* be2   = (const float*)d_in[5];
    const float* Wn1   = (const float*)d_in[6];
    const float* bn1   = (const float*)d_in[7];
    const float* Wn2   = (const float*)d_in[8];
    const float* bn2   = (const float*)d_in[9];
    const int*   esrc  = (const int*)d_in[10];
    const int*   esnk  = (const int*)d_in[11];
    float* out = (float*)d_out;

    k_copy_ns<<<(BB * NN * DD + 1023) / 1024, 1024>>>(nodes);
    k_prep_w<<<(2 * HH * HH + 2 * 256 * HH + 255) / 256, 256>>>(We1, We2, Wn1, Wn2);

    for (int s = 0; s < STEPS; ++s) {
        k_zero_inc<<<(BB * NN * MSG + 1023) / 1024, 1024>>>();
        k_gemm<0><<<dim3(4, (BB * EE) / 128), 256>>>(be1, esrc, esnk);
        k_gemm<1><<<dim3(2, (BB * EE) / 128), 256>>>(be2, esrc, esnk);
        k_gemm<2><<<dim3(4, (BB * NN) / 128), 256>>>(bn1, esrc, esnk);
        k_gemm<3><<<dim3(2, (BB * NN) / 128), 256>>>(bn2, esrc, esnk);
    }

    k_zero_out<<<(out_size + 255) / 256, 256>>>(out, out_size);
    k_extract<<<dim3(2, 8, 8), 256>>>(attn, out);
}

// round 5
// speedup vs baseline: 2.1197x; 1.1787x over previous
#include <cuda_runtime.h>
#include <cuda_bf16.h>
#include <cstdint>

// Problem constants
#define BB   8
#define NN   4096
#define EE   16384
#define PP   64
#define DD   256
#define HH   512
#define MSG  256
#define UPD  254
#define STEPS 3

// ---------------- scratch (device globals) -----------------------------------
__device__ float g_ns[BB * NN * DD];                 // node states fp32 master
__device__ float g_inc[BB * NN * MSG];               // incoming messages (atomics)
// pre-split activations (bf16 hi/lo)
__device__ __nv_bfloat16 g_ns_hi[BB * NN * DD],   g_ns_lo[BB * NN * DD];
__device__ __nv_bfloat16 g_inc_hi[BB * NN * MSG], g_inc_lo[BB * NN * MSG];
__device__ __nv_bfloat16 g_h_hi[(size_t)BB * EE * HH], g_h_lo[(size_t)BB * EE * HH];
// pre-split, pre-transposed weights: [N][K] bf16, hi + lo
__device__ __nv_bfloat16 g_We1T_hi[HH * HH],  g_We1T_lo[HH * HH];
__device__ __nv_bfloat16 g_We2T_hi[MSG * HH], g_We2T_lo[MSG * HH];
__device__ __nv_bfloat16 g_Wn1T_hi[HH * HH],  g_Wn1T_lo[HH * HH];
__device__ __nv_bfloat16 g_Wn2T_hi[256 * HH], g_Wn2T_lo[256 * HH];  // padded N=256

// ---------------- helpers ------------------------------------------------------
__device__ __forceinline__ uint32_t smem_u32(const void* p) {
    uint32_t a;
    asm("{ .reg .u64 t; cvta.to.shared.u64 t, %1; cvt.u32.u64 %0, t; }" : "=r"(a) : "l"(p));
    return a;
}
__device__ __forceinline__ void ldm4(uint32_t* d, uint32_t addr) {
    asm volatile("ldmatrix.sync.aligned.m8n8.x4.shared.b16 {%0,%1,%2,%3}, [%4];"
        : "=r"(d[0]), "=r"(d[1]), "=r"(d[2]), "=r"(d[3]) : "r"(addr) : "memory");
}
__device__ __forceinline__ void mma_bf16(float* d, const uint32_t* a, uint32_t b0, uint32_t b1) {
    asm volatile("mma.sync.aligned.m16n8k16.row.col.f32.bf16.bf16.f32 "
        "{%0,%1,%2,%3}, {%4,%5,%6,%7}, {%8,%9}, {%0,%1,%2,%3};"
        : "+f"(d[0]), "+f"(d[1]), "+f"(d[2]), "+f"(d[3])
        : "r"(a[0]), "r"(a[1]), "r"(a[2]), "r"(a[3]), "r"(b0), "r"(b1));
}
__device__ __forceinline__ void cpa16(uint32_t s, const void* g) {
    asm volatile("cp.async.cg.shared.global [%0], [%1], 16;" :: "r"(s), "l"(g) : "memory");
}
#define CP_COMMIT() asm volatile("cp.async.commit_group;" ::: "memory")
#define CP_WAIT1()  asm volatile("cp.async.wait_group 1;" ::: "memory")
#define CP_WAIT0()  asm volatile("cp.async.wait_group 0;" ::: "memory")

__device__ __forceinline__ void bsplit(float v, __nv_bfloat16& h, __nv_bfloat16& l) {
    h = __float2bfloat16(v);
    l = __float2bfloat16(v - __bfloat162float(h));
}
__device__ __forceinline__ uint32_t pack2(__nv_bfloat16 a, __nv_bfloat16 b) {
    __nv_bfloat162 t2 = __halves2bfloat162(a, b);
    return *reinterpret_cast<uint32_t*>(&t2);
}

// ---------------- small utility kernels --------------------------------------
__global__ void k_copy_ns(const float* __restrict__ src) {
    int i = blockIdx.x * blockDim.x + threadIdx.x;
    if (i < BB * NN * DD) g_ns[i] = src[i];
}
__global__ void k_zero_inc() {
    int i = blockIdx.x * blockDim.x + threadIdx.x;
    if (i < BB * NN * MSG) g_inc[i] = 0.f;
}
__global__ void k_zero_out(float* __restrict__ p, int n) {
    int i = blockIdx.x * blockDim.x + threadIdx.x;
    if (i < n) p[i] = 0.f;
}
__global__ void k_split_ns() {
    int i = blockIdx.x * blockDim.x + threadIdx.x;
    if (i < BB * NN * DD) bsplit(g_ns[i], g_ns_hi[i], g_ns_lo[i]);
}
__global__ void k_split_inc() {
    int i = blockIdx.x * blockDim.x + threadIdx.x;
    if (i < BB * NN * MSG) bsplit(g_inc[i], g_inc_hi[i], g_inc_lo[i]);
}
__global__ void k_prep_w(const float* __restrict__ We1, const float* __restrict__ We2,
                         const float* __restrict__ Wn1, const float* __restrict__ Wn2) {
    int i = blockIdx.x * blockDim.x + threadIdx.x;
    const int S1 = HH * HH, S2 = S1 + MSG * HH, S3 = S2 + HH * HH, S4 = S3 + 256 * HH;
    if (i < S1) {
        int n = i >> 9, k = i & 511;
        bsplit(We1[k * HH + n], g_We1T_hi[i], g_We1T_lo[i]);
    } else if (i < S2) {
        int j = i - S1; int n = j >> 9, k = j & 511;
        bsplit(We2[k * MSG + n], g_We2T_hi[j], g_We2T_lo[j]);
    } else if (i < S3) {
        int j = i - S2; int n = j >> 9, k = j & 511;
        bsplit(Wn1[k * HH + n], g_Wn1T_hi[j], g_Wn1T_lo[j]);
    } else if (i < S4) {
        int j = i - S3; int n = j >> 9, k = j & 511;
        float v = (n < UPD) ? Wn2[k * UPD + n] : 0.f;
        bsplit(v, g_Wn2T_hi[j], g_Wn2T_lo[j]);
    }
}

// ---------------- smem tile layout --------------------------------------------
// per-buffer: 4 regions of 128 rows x 32 bf16, row stride 40 bf16 = 80 B
#define RS 40
#define A_HI 0
#define A_LO 10240
#define B_HI 20480
#define B_LO 30720
#define BUF_SZ 40960
#define SM_DYN (2 * BUF_SZ)

// async A tile: 128 rows x 32 bf16 from pre-split pair, row base table
__device__ __forceinline__ void loadA_async(uint32_t sb,
                                            const __nv_bfloat16* __restrict__ hi,
                                            const __nv_bfloat16* __restrict__ lo,
                                            const int* __restrict__ rb,
                                            int colbase, int t) {
#pragma unroll
    for (int i = 0; i < 2; ++i) {
        int f = t + i * 256;
        int row = f >> 2, seg = f & 3;
        int off = row * (RS * 2) + seg * 16;
        size_t src = (size_t)rb[row] + colbase + seg * 8;
        cpa16(sb + A_HI + off, hi + src);
        cpa16(sb + A_LO + off, lo + src);
    }
}
// async B tile: 128 n-rows x 32 k from pre-split transposed weights [n][512]
__device__ __forceinline__ void loadB_async(uint32_t sb,
                                            const __nv_bfloat16* __restrict__ Whi,
                                            const __nv_bfloat16* __restrict__ Wlo,
                                            int n0, int k0, int t) {
#pragma unroll
    for (int i = 0; i < 2; ++i) {
        int f = t + i * 256;
        int row = f >> 2, seg = f & 3;
        int off = row * (RS * 2) + seg * 16;
        size_t src = (size_t)(n0 + row) * HH + k0 + seg * 8;
        cpa16(sb + B_HI + off, Whi + src);
        cpa16(sb + B_LO + off, Wlo + src);
    }
}

// ---------------- unified HMMA GEMM kernel (cp.async double-buffered) ---------
// MODE 0: edge1  relu(gather(src|snk) @ We1 + b) -> g_h split    grid(4,1024)
// MODE 1: edge2  (g_h @ We2 + b) scatter-atomic -> g_inc         grid(2,1024)
// MODE 2: node1  relu([inc|ns] @ Wn1 + b) -> g_h split           grid(4,256)
// MODE 3: node2  g_ns[...,2:256] += (g_h @ Wn2p + b)             grid(2,256)
template<int MODE>
__global__ void __launch_bounds__(256)
k_gemm(const float* __restrict__ bias,
       const int* __restrict__ esrc, const int* __restrict__ esnk) {
    extern __shared__ char sm[];
    __shared__ int tab0[128], tab1[128];
    const int t = threadIdx.x, l = t & 31, wid = t >> 5;
    const int wm = wid >> 2, wn = wid & 3;
    const int n0 = blockIdx.x * 128, r0 = blockIdx.y * 128;

    if (t < 128) {
        int r = r0 + t;
        if (MODE == 0) {
            int b = r >> 14, e = r & (EE - 1);
            tab0[t] = ((b << 12) + __ldg(esrc + e)) << 8;
            tab1[t] = ((b << 12) + __ldg(esnk + e)) << 8;
        } else if (MODE == 1) {
            int b = r >> 14, e = r & (EE - 1);
            tab0[t] = r * HH;
            tab1[t] = ((b << 12) + __ldg(esnk + e)) << 8;   // scatter dest in g_inc
        } else if (MODE == 2) {
            tab0[t] = r * DD;
        } else {
            tab0[t] = r * HH;
        }
    }
    __syncthreads();

    const __nv_bfloat16 *Whi, *Wlo;
    if (MODE == 0)      { Whi = g_We1T_hi; Wlo = g_We1T_lo; }
    else if (MODE == 1) { Whi = g_We2T_hi; Wlo = g_We2T_lo; }
    else if (MODE == 2) { Whi = g_Wn1T_hi; Wlo = g_Wn1T_lo; }
    else                { Whi = g_Wn2T_hi; Wlo = g_Wn2T_lo; }

    uint32_t smb = smem_u32(sm);

    // per-chunk A source resolver
    auto issue = [&](int c) {
        uint32_t sb = smb + (c & 1) * BUF_SZ;
        const __nv_bfloat16 *ahi, *alo; const int* rb; int cb;
        if (MODE == 0) {
            ahi = g_ns_hi; alo = g_ns_lo; rb = (c < 8) ? tab0 : tab1; cb = (c & 7) * 32;
        } else if (MODE == 2) {
            if (c < 8) { ahi = g_inc_hi; alo = g_inc_lo; }
            else       { ahi = g_ns_hi;  alo = g_ns_lo; }
            rb = tab0; cb = (c & 7) * 32;
        } else {
            ahi = g_h_hi; alo = g_h_lo; rb = tab0; cb = c * 32;
        }
        loadA_async(sb, ahi, alo, rb, cb, t);
        loadB_async(sb, Whi, Wlo, n0, c * 32, t);
        CP_COMMIT();
    };

    float acc[4][4][4] = {};
    const int lrow8 = (((l >> 3) & 1) << 3) + (l & 7);
    const int lcol8 = (l >> 4) << 3;

    issue(0);
    for (int c = 0; c < 16; ++c) {
        if (c < 15) issue(c + 1);
        if (c < 15) { CP_WAIT1(); } else { CP_WAIT0(); }
        __syncthreads();
        uint32_t sb = smb + (c & 1) * BUF_SZ;
#pragma unroll
        for (int ks = 0; ks < 2; ++ks) {
            uint32_t Af[4][4], Bh[2][4], Bl[2][4];
            const int kcol = ks * 16 + lcol8;
#pragma unroll
            for (int i = 0; i < 4; ++i)
                ldm4(Af[i], sb + A_HI + ((wm * 64 + i * 16 + lrow8) * RS + kcol) * 2);
#pragma unroll
            for (int g = 0; g < 2; ++g) {
                ldm4(Bh[g], sb + B_HI + ((wn * 32 + g * 16 + lrow8) * RS + kcol) * 2);
                ldm4(Bl[g], sb + B_LO + ((wn * 32 + g * 16 + lrow8) * RS + kcol) * 2);
            }
#pragma unroll
            for (int i = 0; i < 4; ++i)
#pragma unroll
                for (int j = 0; j < 4; ++j) {
                    mma_bf16(acc[i][j], Af[i], Bh[j >> 1][j & 1], Bh[j >> 1][(j & 1) + 2]);
                    mma_bf16(acc[i][j], Af[i], Bl[j >> 1][j & 1], Bl[j >> 1][(j & 1) + 2]);
                }
#pragma unroll
            for (int i = 0; i < 4; ++i)
                ldm4(Af[i], sb + A_LO + ((wm * 64 + i * 16 + lrow8) * RS + kcol) * 2);
#pragma unroll
            for (int i = 0; i < 4; ++i)
#pragma unroll
                for (int j = 0; j < 4; ++j)
                    mma_bf16(acc[i][j], Af[i], Bh[j >> 1][j & 1], Bh[j >> 1][(j & 1) + 2]);
        }
        __syncthreads();   // all warps done with buf (c&1) before it is refilled
    }

    // ---------------- epilogue ----------------
#pragma unroll
    for (int i = 0; i < 4; ++i) {
        const int rl = wm * 64 + i * 16 + (l >> 2);
#pragma unroll
        for (int j = 0; j < 4; ++j) {
            const int c = n0 + wn * 32 + j * 8 + ((l & 3) << 1);
            if (MODE == 0 || MODE == 2) {
                float b0 = __ldg(bias + c), b1 = __ldg(bias + c + 1);
                size_t ro0 = (size_t)(r0 + rl) * HH + c;
                size_t ro1 = (size_t)(r0 + rl + 8) * HH + c;
                float v0 = fmaxf(acc[i][j][0] + b0, 0.f);
                float v1 = fmaxf(acc[i][j][1] + b1, 0.f);
                float v2 = fmaxf(acc[i][j][2] + b0, 0.f);
                float v3 = fmaxf(acc[i][j][3] + b1, 0.f);
                __nv_bfloat16 h0, h1, h2, h3, q0, q1, q2, q3;
                bsplit(v0, h0, q0); bsplit(v1, h1, q1);
                bsplit(v2, h2, q2); bsplit(v3, h3, q3);
                *(uint32_t*)(g_h_hi + ro0) = pack2(h0, h1);
                *(uint32_t*)(g_h_lo + ro0) = pack2(q0, q1);
                *(uint32_t*)(g_h_hi + ro1) = pack2(h2, h3);
                *(uint32_t*)(g_h_lo + ro1) = pack2(q2, q3);
            } else if (MODE == 1) {
                float b0 = __ldg(bias + c), b1 = __ldg(bias + c + 1);
                int d0 = tab1[rl], d1 = tab1[rl + 8];
                atomicAdd(g_inc + d0 + c,     acc[i][j][0] + b0);
                atomicAdd(g_inc + d0 + c + 1, acc[i][j][1] + b1);
                atomicAdd(g_inc + d1 + c,     acc[i][j][2] + b0);
                atomicAdd(g_inc + d1 + c + 1, acc[i][j][3] + b1);
            } else {
                float b0 = (c < UPD)     ? __ldg(bias + c)     : 0.f;
                float b1 = (c + 1 < UPD) ? __ldg(bias + c + 1) : 0.f;
                size_t ro0 = (size_t)(r0 + rl) * DD + 2;
                size_t ro1 = (size_t)(r0 + rl + 8) * DD + 2;
                if (c < UPD)     g_ns[ro0 + c]     += acc[i][j][0] + b0;
                if (c + 1 < UPD) g_ns[ro0 + c + 1] += acc[i][j][1] + b1;
                if (c < UPD)     g_ns[ro1 + c]     += acc[i][j][2] + b0;
                if (c + 1 < UPD) g_ns[ro1 + c + 1] += acc[i][j][3] + b1;
            }
        }
    }
}

// ---------------- extraction (batched attn @ ns, split-K, SIMT) --------------
__global__ void __launch_bounds__(256)
k_extract(const float* __restrict__ attn, float* __restrict__ out) {
    __shared__ float As[32 * 68];
    __shared__ float Bs[32 * 128];
    int t = threadIdx.x;
    int n0 = blockIdx.x * 128;
    int kbase = blockIdx.y * 512;
    int b = blockIdx.z;
    int ty = t >> 4, tx = t & 15;
    float acc[4][8] = {};
    for (int kt = 0; kt < 16; ++kt) {
        int kabs = kbase + kt * 32;
#pragma unroll
        for (int i = 0; i < 2; ++i) {
            int f = t + i * 256;
            int row = f >> 3;
            int kq = (f & 7) << 2;
            float4 v = *(const float4*)(attn + ((size_t)(b * PP + row)) * NN + kabs + kq);
            As[(kq + 0) * 68 + row] = v.x;
            As[(kq + 1) * 68 + row] = v.y;
            As[(kq + 2) * 68 + row] = v.z;
            As[(kq + 3) * 68 + row] = v.w;
        }
#pragma unroll
        for (int i = 0; i < 4; ++i) {
            int f = t + i * 256;
            int k = f >> 5;
            int c = (f & 31) << 2;
            *(float4*)(Bs + k * 128 + c) =
                *(const float4*)(g_ns + ((size_t)(b * NN + kabs + k)) * DD + n0 + c);
        }
        __syncthreads();
#pragma unroll
        for (int k = 0; k < 32; ++k) {
            float4 a = *(const float4*)(As + k * 68 + ty * 4);
            float4 b0 = *(const float4*)(Bs + k * 128 + tx * 8);
            float4 b1 = *(const float4*)(Bs + k * 128 + tx * 8 + 4);
            float av[4] = {a.x, a.y, a.z, a.w};
            float bv[8] = {b0.x, b0.y, b0.z, b0.w, b1.x, b1.y, b1.z, b1.w};
#pragma unroll
            for (int i = 0; i < 4; ++i)
#pragma unroll
                for (int j = 0; j < 8; ++j)
                    acc[i][j] = fmaf(av[i], bv[j], acc[i][j]);
        }
        __syncthreads();
    }
#pragma unroll
    for (int i = 0; i < 4; ++i)
#pragma unroll
        for (int j = 0; j < 8; ++j)
            atomicAdd(&out[((size_t)(b * PP + ty * 4 + i)) * DD + n0 + tx * 8 + j],
                      acc[i][j]);
}

// ---------------- launcher ----------------------------------------------------
extern "C" void kernel_launch(void* const* d_in, const int* in_sizes, int n_in,
                              void* d_out, int out_size) {
    const float* nodes = (const float*)d_in[0];
    const float* attn  = (const float*)d_in[1];
    const float* We1   = (const float*)d_in[2];
    const float* be1   = (const float*)d_in[3];
    const float* We2   = (const float*)d_in[4];
    const float* be2   = (const float*)d_in[5];
    const float* Wn1   = (const float*)d_in[6];
    const float* bn1   = (const float*)d_in[7];
    const float* Wn2   = (const float*)d_in[8];
    const float* bn2   = (const float*)d_in[9];
    const int*   esrc  = (const int*)d_in[10];
    const int*   esnk  = (const int*)d_in[11];
    float* out = (float*)d_out;

    cudaFuncSetAttribute(k_gemm<0>, cudaFuncAttributeMaxDynamicSharedMemorySize, SM_DYN);
    cudaFuncSetAttribute(k_gemm<1>, cudaFuncAttributeMaxDynamicSharedMemorySize, SM_DYN);
    cudaFuncSetAttribute(k_gemm<2>, cudaFuncAttributeMaxDynamicSharedMemorySize, SM_DYN);
    cudaFuncSetAttribute(k_gemm<3>, cudaFuncAttributeMaxDynamicSharedMemorySize, SM_DYN);

    k_copy_ns<<<(BB * NN * DD + 1023) / 1024, 1024>>>(nodes);
    k_prep_w<<<(2 * HH * HH + 2 * 256 * HH + 255) / 256, 256>>>(We1, We2, Wn1, Wn2);

    for (int s = 0; s < STEPS; ++s) {
        k_zero_inc<<<(BB * NN * MSG + 1023) / 1024, 1024>>>();
        k_split_ns<<<(BB * NN * DD + 1023) / 1024, 1024>>>();
        k_gemm<0><<<dim3(4, (BB * EE) / 128), 256, SM_DYN>>>(be1, esrc, esnk);
        k_gemm<1><<<dim3(2, (BB * EE) / 128), 256, SM_DYN>>>(be2, esrc, esnk);
        k_split_inc<<<(BB * NN * MSG + 1023) / 1024, 1024>>>();
        k_gemm<2><<<dim3(4, (BB * NN) / 128), 256, SM_DYN>>>(bn1, esrc, esnk);
        k_gemm<3><<<dim3(2, (BB * NN) / 128), 256, SM_DYN>>>(bn2, esrc, esnk);
    }

    k_zero_out<<<(out_size + 255) / 256, 256>>>(out, out_size);
    k_extract<<<dim3(2, 8, 8), 256>>>(attn, out);
}

// round 6
// speedup vs baseline: 2.4359x; 1.1492x over previous
#include <cuda_runtime.h>
#include <cuda_bf16.h>
#include <cstdint>

// Problem constants
#define BB   8
#define NN   4096
#define EE   16384
#define PP   64
#define DD   256
#define HH   512
#define MSG  256
#define UPD  254
#define STEPS 3

// ---------------- scratch (device globals) -----------------------------------
__device__ float g_ns[BB * NN * DD];                 // node states fp32 master
__device__ float g_inc[BB * NN * MSG];               // incoming messages (atomics)
// pre-split activations (bf16 hi/lo)
__device__ __nv_bfloat16 g_ns_hi[BB * NN * DD],   g_ns_lo[BB * NN * DD];
__device__ __nv_bfloat16 g_inc_hi[BB * NN * MSG], g_inc_lo[BB * NN * MSG];
__device__ __nv_bfloat16 g_h_hi[(size_t)BB * EE * HH], g_h_lo[(size_t)BB * EE * HH];
// pre-split, pre-transposed weights: [N][K] bf16, hi + lo
__device__ __nv_bfloat16 g_We1T_hi[HH * HH],  g_We1T_lo[HH * HH];
__device__ __nv_bfloat16 g_We2T_hi[MSG * HH], g_We2T_lo[MSG * HH];
__device__ __nv_bfloat16 g_Wn1T_hi[HH * HH],  g_Wn1T_lo[HH * HH];
__device__ __nv_bfloat16 g_Wn2T_hi[256 * HH], g_Wn2T_lo[256 * HH];  // padded N=256

// ---------------- helpers ------------------------------------------------------
__device__ __forceinline__ uint32_t smem_u32(const void* p) {
    uint32_t a;
    asm("{ .reg .u64 t; cvta.to.shared.u64 t, %1; cvt.u32.u64 %0, t; }" : "=r"(a) : "l"(p));
    return a;
}
__device__ __forceinline__ void ldm4(uint32_t* d, uint32_t addr) {
    asm volatile("ldmatrix.sync.aligned.m8n8.x4.shared.b16 {%0,%1,%2,%3}, [%4];"
        : "=r"(d[0]), "=r"(d[1]), "=r"(d[2]), "=r"(d[3]) : "r"(addr) : "memory");
}
__device__ __forceinline__ void mma_bf16(float* d, const uint32_t* a, uint32_t b0, uint32_t b1) {
    asm volatile("mma.sync.aligned.m16n8k16.row.col.f32.bf16.bf16.f32 "
        "{%0,%1,%2,%3}, {%4,%5,%6,%7}, {%8,%9}, {%0,%1,%2,%3};"
        : "+f"(d[0]), "+f"(d[1]), "+f"(d[2]), "+f"(d[3])
        : "r"(a[0]), "r"(a[1]), "r"(a[2]), "r"(a[3]), "r"(b0), "r"(b1));
}
__device__ __forceinline__ void cpa16(uint32_t s, const void* g) {
    asm volatile("cp.async.cg.shared.global [%0], [%1], 16;" :: "r"(s), "l"(g) : "memory");
}
#define CP_COMMIT() asm volatile("cp.async.commit_group;" ::: "memory")
#define CP_WAIT1()  asm volatile("cp.async.wait_group 1;" ::: "memory")
#define CP_WAIT0()  asm volatile("cp.async.wait_group 0;" ::: "memory")

__device__ __forceinline__ void bsplit(float v, __nv_bfloat16& h, __nv_bfloat16& l) {
    h = __float2bfloat16(v);
    l = __float2bfloat16(v - __bfloat162float(h));
}
__device__ __forceinline__ uint32_t pack2(__nv_bfloat16 a, __nv_bfloat16 b) {
    __nv_bfloat162 t2 = __halves2bfloat162(a, b);
    return *reinterpret_cast<uint32_t*>(&t2);
}

// ---------------- small utility kernels --------------------------------------
__global__ void k_copy_ns(const float* __restrict__ src) {
    int i = blockIdx.x * blockDim.x + threadIdx.x;
    if (i < BB * NN * DD) g_ns[i] = src[i];
}
__global__ void k_zero_inc() {
    int i = blockIdx.x * blockDim.x + threadIdx.x;
    if (i < BB * NN * MSG) g_inc[i] = 0.f;
}
__global__ void k_zero_out(float* __restrict__ p, int n) {
    int i = blockIdx.x * blockDim.x + threadIdx.x;
    if (i < n) p[i] = 0.f;
}
__global__ void k_split_ns() {
    int i = blockIdx.x * blockDim.x + threadIdx.x;
    if (i < BB * NN * DD) bsplit(g_ns[i], g_ns_hi[i], g_ns_lo[i]);
}
__global__ void k_split_inc() {
    int i = blockIdx.x * blockDim.x + threadIdx.x;
    if (i < BB * NN * MSG) bsplit(g_inc[i], g_inc_hi[i], g_inc_lo[i]);
}
__global__ void k_prep_w(const float* __restrict__ We1, const float* __restrict__ We2,
                         const float* __restrict__ Wn1, const float* __restrict__ Wn2) {
    int i = blockIdx.x * blockDim.x + threadIdx.x;
    const int S1 = HH * HH, S2 = S1 + MSG * HH, S3 = S2 + HH * HH, S4 = S3 + 256 * HH;
    if (i < S1) {
        int n = i >> 9, k = i & 511;
        bsplit(We1[k * HH + n], g_We1T_hi[i], g_We1T_lo[i]);
    } else if (i < S2) {
        int j = i - S1; int n = j >> 9, k = j & 511;
        bsplit(We2[k * MSG + n], g_We2T_hi[j], g_We2T_lo[j]);
    } else if (i < S3) {
        int j = i - S2; int n = j >> 9, k = j & 511;
        bsplit(Wn1[k * HH + n], g_Wn1T_hi[j], g_Wn1T_lo[j]);
    } else if (i < S4) {
        int j = i - S3; int n = j >> 9, k = j & 511;
        float v = (n < UPD) ? Wn2[k * UPD + n] : 0.f;
        bsplit(v, g_Wn2T_hi[j], g_Wn2T_lo[j]);
    }
}

// ---------------- smem tile layout (XOR swizzle, 64B rows) --------------------
// region: 128 rows x 32 bf16 (64 B/row) = 8 KB; element (r, c):
//   byte = r*64 + ((c/8 ^ ((r>>1)&3))*16) + (c%8)*2   -> conflict-free ldmatrix
#define A_HI 0
#define A_LO 8192
#define B_HI 16384
#define B_LO 24576
#define BUF_SZ 32768
#define NSTAGE 3
#define SM_DYN (NSTAGE * BUF_SZ)

__device__ __forceinline__ uint32_t swz(int r, int c0) {
    return (uint32_t)(r * 64 + ((((c0 >> 3) ^ ((r >> 1) & 3)) << 4)));
}

// async A tile: 128 rows x 32 bf16 from pre-split pair, row base table
__device__ __forceinline__ void loadA_async(uint32_t sb,
                                            const __nv_bfloat16* __restrict__ hi,
                                            const __nv_bfloat16* __restrict__ lo,
                                            const int* __restrict__ rb,
                                            int colbase, int t) {
#pragma unroll
    for (int i = 0; i < 2; ++i) {
        int f = t + i * 256;
        int row = f >> 2, seg = f & 3;
        uint32_t off = swz(row, seg * 8);
        size_t src = (size_t)rb[row] + colbase + seg * 8;
        cpa16(sb + A_HI + off, hi + src);
        cpa16(sb + A_LO + off, lo + src);
    }
}
// async B tile: 128 n-rows x 32 k from pre-split transposed weights [n][512]
__device__ __forceinline__ void loadB_async(uint32_t sb,
                                            const __nv_bfloat16* __restrict__ Whi,
                                            const __nv_bfloat16* __restrict__ Wlo,
                                            int n0, int k0, int t) {
#pragma unroll
    for (int i = 0; i < 2; ++i) {
        int f = t + i * 256;
        int row = f >> 2, seg = f & 3;
        uint32_t off = swz(row, seg * 8);
        size_t src = (size_t)(n0 + row) * HH + k0 + seg * 8;
        cpa16(sb + B_HI + off, Whi + src);
        cpa16(sb + B_LO + off, Wlo + src);
    }
}

// ---------------- unified HMMA GEMM kernel (3-stage cp.async) -----------------
// MODE 0: edge1  relu(gather(src|snk) @ We1 + b) -> g_h split    grid(4,1024)
// MODE 1: edge2  (g_h @ We2 + b) scatter-atomic -> g_inc         grid(2,1024)
// MODE 2: node1  relu([inc|ns] @ Wn1 + b) -> g_h split           grid(4,256)
// MODE 3: node2  g_ns[...,2:256] += upd (fp32 + re-split)        grid(2,256)
template<int MODE>
__global__ void __launch_bounds__(256)
k_gemm(const float* __restrict__ bias,
       const int* __restrict__ esrc, const int* __restrict__ esnk) {
    extern __shared__ char sm[];
    __shared__ int tab0[128], tab1[128];
    const int t = threadIdx.x, l = t & 31, wid = t >> 5;
    const int wm = wid >> 2, wn = wid & 3;
    const int n0 = blockIdx.x * 128, r0 = blockIdx.y * 128;

    if (t < 128) {
        int r = r0 + t;
        if (MODE == 0) {
            int b = r >> 14, e = r & (EE - 1);
            tab0[t] = ((b << 12) + __ldg(esrc + e)) << 8;
            tab1[t] = ((b << 12) + __ldg(esnk + e)) << 8;
        } else if (MODE == 1) {
            int b = r >> 14, e = r & (EE - 1);
            tab0[t] = r * HH;
            tab1[t] = ((b << 12) + __ldg(esnk + e)) << 8;   // scatter dest in g_inc
        } else if (MODE == 2) {
            tab0[t] = r * DD;
        } else {
            tab0[t] = r * HH;
        }
    }
    __syncthreads();

    const __nv_bfloat16 *Whi, *Wlo;
    if (MODE == 0)      { Whi = g_We1T_hi; Wlo = g_We1T_lo; }
    else if (MODE == 1) { Whi = g_We2T_hi; Wlo = g_We2T_lo; }
    else if (MODE == 2) { Whi = g_Wn1T_hi; Wlo = g_Wn1T_lo; }
    else                { Whi = g_Wn2T_hi; Wlo = g_Wn2T_lo; }

    uint32_t smb = smem_u32(sm);

    auto issue = [&](int c) {
        uint32_t sb = smb + (c % NSTAGE) * BUF_SZ;
        const __nv_bfloat16 *ahi, *alo; const int* rb; int cb;
        if (MODE == 0) {
            ahi = g_ns_hi; alo = g_ns_lo; rb = (c < 8) ? tab0 : tab1; cb = (c & 7) * 32;
        } else if (MODE == 2) {
            if (c < 8) { ahi = g_inc_hi; alo = g_inc_lo; }
            else       { ahi = g_ns_hi;  alo = g_ns_lo; }
            rb = tab0; cb = (c & 7) * 32;
        } else {
            ahi = g_h_hi; alo = g_h_lo; rb = tab0; cb = c * 32;
        }
        loadA_async(sb, ahi, alo, rb, cb, t);
        loadB_async(sb, Whi, Wlo, n0, c * 32, t);
        CP_COMMIT();
    };

    float acc[4][4][4] = {};
    const int lrow8 = (((l >> 3) & 1) << 3) + (l & 7);
    const int lcol8 = (l >> 4) << 3;

    issue(0); issue(1);
    for (int c = 0; c < 16; ++c) {
        if (c < 15) { CP_WAIT1(); } else { CP_WAIT0(); }
        __syncthreads();
        if (c < 14) issue(c + 2);
        uint32_t sb = smb + (c % NSTAGE) * BUF_SZ;
#pragma unroll
        for (int ks = 0; ks < 2; ++ks) {
            uint32_t Af[4][4], Bh[2][4], Bl[2][4];
            const int kcol = ks * 16 + lcol8;
#pragma unroll
            for (int i = 0; i < 4; ++i)
                ldm4(Af[i], sb + A_HI + swz(wm * 64 + i * 16 + lrow8, kcol));
#pragma unroll
            for (int g = 0; g < 2; ++g) {
                ldm4(Bh[g], sb + B_HI + swz(wn * 32 + g * 16 + lrow8, kcol));
                ldm4(Bl[g], sb + B_LO + swz(wn * 32 + g * 16 + lrow8, kcol));
            }
#pragma unroll
            for (int i = 0; i < 4; ++i)
#pragma unroll
                for (int j = 0; j < 4; ++j) {
                    mma_bf16(acc[i][j], Af[i], Bh[j >> 1][j & 1], Bh[j >> 1][(j & 1) + 2]);
                    mma_bf16(acc[i][j], Af[i], Bl[j >> 1][j & 1], Bl[j >> 1][(j & 1) + 2]);
                }
#pragma unroll
            for (int i = 0; i < 4; ++i)
                ldm4(Af[i], sb + A_LO + swz(wm * 64 + i * 16 + lrow8, kcol));
#pragma unroll
            for (int i = 0; i < 4; ++i)
#pragma unroll
                for (int j = 0; j < 4; ++j)
                    mma_bf16(acc[i][j], Af[i], Bh[j >> 1][j & 1], Bh[j >> 1][(j & 1) + 2]);
        }
    }

    // ---------------- epilogue ----------------
#pragma unroll
    for (int i = 0; i < 4; ++i) {
        const int rl = wm * 64 + i * 16 + (l >> 2);
#pragma unroll
        for (int j = 0; j < 4; ++j) {
            const int c = n0 + wn * 32 + j * 8 + ((l & 3) << 1);
            if (MODE == 0 || MODE == 2) {
                float b0 = __ldg(bias + c), b1 = __ldg(bias + c + 1);
                size_t ro0 = (size_t)(r0 + rl) * HH + c;
                size_t ro1 = (size_t)(r0 + rl + 8) * HH + c;
                float v0 = fmaxf(acc[i][j][0] + b0, 0.f);
                float v1 = fmaxf(acc[i][j][1] + b1, 0.f);
                float v2 = fmaxf(acc[i][j][2] + b0, 0.f);
                float v3 = fmaxf(acc[i][j][3] + b1, 0.f);
                __nv_bfloat16 h0, h1, h2, h3, q0, q1, q2, q3;
                bsplit(v0, h0, q0); bsplit(v1, h1, q1);
                bsplit(v2, h2, q2); bsplit(v3, h3, q3);
                *(uint32_t*)(g_h_hi + ro0) = pack2(h0, h1);
                *(uint32_t*)(g_h_lo + ro0) = pack2(q0, q1);
                *(uint32_t*)(g_h_hi + ro1) = pack2(h2, h3);
                *(uint32_t*)(g_h_lo + ro1) = pack2(q2, q3);
            } else if (MODE == 1) {
                float b0 = __ldg(bias + c), b1 = __ldg(bias + c + 1);
                int d0 = tab1[rl], d1 = tab1[rl + 8];
                atomicAdd(g_inc + d0 + c,     acc[i][j][0] + b0);
                atomicAdd(g_inc + d0 + c + 1, acc[i][j][1] + b1);
                atomicAdd(g_inc + d1 + c,     acc[i][j][2] + b0);
                atomicAdd(g_inc + d1 + c + 1, acc[i][j][3] + b1);
            } else {
                // node2: update fp32 master AND refresh split copies
                size_t ro0 = (size_t)(r0 + rl) * DD + 2;
                size_t ro1 = (size_t)(r0 + rl + 8) * DD + 2;
#pragma unroll
                for (int q = 0; q < 2; ++q) {
                    int cg = c + q;
                    if (cg < UPD) {
                        float bq = __ldg(bias + cg);
                        float nv0 = g_ns[ro0 + cg] + acc[i][j][q] + bq;
                        float nv1 = g_ns[ro1 + cg] + acc[i][j][q + 2] + bq;
                        g_ns[ro0 + cg] = nv0;
                        g_ns[ro1 + cg] = nv1;
                        __nv_bfloat16 h, lo;
                        bsplit(nv0, h, lo);
                        g_ns_hi[ro0 + cg] = h; g_ns_lo[ro0 + cg] = lo;
                        bsplit(nv1, h, lo);
                        g_ns_hi[ro1 + cg] = h; g_ns_lo[ro1 + cg] = lo;
                    }
                }
            }
        }
    }
}

// ---------------- extraction (batched attn @ ns, split-K, SIMT) --------------
__global__ void __launch_bounds__(256)
k_extract(const float* __restrict__ attn, float* __restrict__ out) {
    __shared__ float As[32 * 68];
    __shared__ float Bs[32 * 128];
    int t = threadIdx.x;
    int n0 = blockIdx.x * 128;
    int kbase = blockIdx.y * 512;
    int b = blockIdx.z;
    int ty = t >> 4, tx = t & 15;
    float acc[4][8] = {};
    for (int kt = 0; kt < 16; ++kt) {
        int kabs = kbase + kt * 32;
#pragma unroll
        for (int i = 0; i < 2; ++i) {
            int f = t + i * 256;
            int row = f >> 3;
            int kq = (f & 7) << 2;
            float4 v = *(const float4*)(attn + ((size_t)(b * PP + row)) * NN + kabs + kq);
            As[(kq + 0) * 68 + row] = v.x;
            As[(kq + 1) * 68 + row] = v.y;
            As[(kq + 2) * 68 + row] = v.z;
            As[(kq + 3) * 68 + row] = v.w;
        }
#pragma unroll
        for (int i = 0; i < 4; ++i) {
            int f = t + i * 256;
            int k = f >> 5;
            int c = (f & 31) << 2;
            *(float4*)(Bs + k * 128 + c) =
                *(const float4*)(g_ns + ((size_t)(b * NN + kabs + k)) * DD + n0 + c);
        }
        __syncthreads();
#pragma unroll
        for (int k = 0; k < 32; ++k) {
            float4 a = *(const float4*)(As + k * 68 + ty * 4);
            float4 b0 = *(const float4*)(Bs + k * 128 + tx * 8);
            float4 b1 = *(const float4*)(Bs + k * 128 + tx * 8 + 4);
            float av[4] = {a.x, a.y, a.z, a.w};
            float bv[8] = {b0.x, b0.y, b0.z, b0.w, b1.x, b1.y, b1.z, b1.w};
#pragma unroll
            for (int i = 0; i < 4; ++i)
#pragma unroll
                for (int j = 0; j < 8; ++j)
                    acc[i][j] = fmaf(av[i], bv[j], acc[i][j]);
        }
        __syncthreads();
    }
#pragma unroll
    for (int i = 0; i < 4; ++i)
#pragma unroll
        for (int j = 0; j < 8; ++j)
            atomicAdd(&out[((size_t)(b * PP + ty * 4 + i)) * DD + n0 + tx * 8 + j],
                      acc[i][j]);
}

// ---------------- launcher ----------------------------------------------------
extern "C" void kernel_launch(void* const* d_in, const int* in_sizes, int n_in,
                              void* d_out, int out_size) {
    const float* nodes = (const float*)d_in[0];
    const float* attn  = (const float*)d_in[1];
    const float* We1   = (const float*)d_in[2];
    const float* be1   = (const float*)d_in[3];
    const float* We2   = (const float*)d_in[4];
    const float* be2   = (const float*)d_in[5];
    const float* Wn1   = (const float*)d_in[6];
    const float* bn1   = (const float*)d_in[7];
    const float* Wn2   = (const float*)d_in[8];
    const float* bn2   = (const float*)d_in[9];
    const int*   esrc  = (const int*)d_in[10];
    const int*   esnk  = (const int*)d_in[11];
    float* out = (float*)d_out;

    cudaFuncSetAttribute(k_gemm<0>, cudaFuncAttributeMaxDynamicSharedMemorySize, SM_DYN);
    cudaFuncSetAttribute(k_gemm<1>, cudaFuncAttributeMaxDynamicSharedMemorySize, SM_DYN);
    cudaFuncSetAttribute(k_gemm<2>, cudaFuncAttributeMaxDynamicSharedMemorySize, SM_DYN);
    cudaFuncSetAttribute(k_gemm<3>, cudaFuncAttributeMaxDynamicSharedMemorySize, SM_DYN);

    k_copy_ns<<<(BB * NN * DD + 1023) / 1024, 1024>>>(nodes);
    k_prep_w<<<(2 * HH * HH + 2 * 256 * HH + 255) / 256, 256>>>(We1, We2, Wn1, Wn2);
    k_split_ns<<<(BB * NN * DD + 1023) / 1024, 1024>>>();   // once; node2 keeps it fresh

    for (int s = 0; s < STEPS; ++s) {
        k_zero_inc<<<(BB * NN * MSG + 1023) / 1024, 1024>>>();
        k_gemm<0><<<dim3(4, (BB * EE) / 128), 256, SM_DYN>>>(be1, esrc, esnk);
        k_gemm<1><<<dim3(2, (BB * EE) / 128), 256, SM_DYN>>>(be2, esrc, esnk);
        k_split_inc<<<(BB * NN * MSG + 1023) / 1024, 1024>>>();
        k_gemm<2><<<dim3(4, (BB * NN) / 128), 256, SM_DYN>>>(bn1, esrc, esnk);
        k_gemm<3><<<dim3(2, (BB * NN) / 128), 256, SM_DYN>>>(bn2, esrc, esnk);
    }

    k_zero_out<<<(out_size + 255) / 256, 256>>>(out, out_size);
    k_extract<<<dim3(2, 8, 8), 256>>>(attn, out);
}

// round 15
// speedup vs baseline: 5.2366x; 2.1497x over previous
#include <cuda_runtime.h>
#include <cuda_fp16.h>
#include <cstdint>

// Problem constants
#define BB   8
#define NN   4096
#define EE   16384
#define PP   64
#define DD   256
#define HH   512
#define MSG  256
#define UPD  254
#define STEPS 3

// ---------------- scratch (device globals) -----------------------------------
__device__ float g_ns[BB * NN * DD];                 // node states fp32 master
__device__ float g_inc[BB * NN * MSG];               // incoming messages (atomics)
// fp16 shadow activations
__device__ __half g_ns_h[BB * NN * DD];
__device__ __half g_inc_h[BB * NN * MSG];
__device__ __half g_h16[(size_t)BB * EE * HH];
// pre-transposed fp16 weights: [N][K]
__device__ __half g_We1T[HH * HH];
__device__ __half g_We2T[MSG * HH];
__device__ __half g_Wn1T[HH * HH];
__device__ __half g_Wn2T[256 * HH];                  // padded N=256

// ---------------- helpers ------------------------------------------------------
__device__ __forceinline__ uint32_t smem_u32(const void* p) {
    uint32_t a;
    asm("{ .reg .u64 t; cvta.to.shared.u64 t, %1; cvt.u32.u64 %0, t; }" : "=r"(a) : "l"(p));
    return a;
}
__device__ __forceinline__ void ldm4(uint32_t* d, uint32_t addr) {
    asm volatile("ldmatrix.sync.aligned.m8n8.x4.shared.b16 {%0,%1,%2,%3}, [%4];"
        : "=r"(d[0]), "=r"(d[1]), "=r"(d[2]), "=r"(d[3]) : "r"(addr) : "memory");
}
__device__ __forceinline__ void mma_f16(float* d, const uint32_t* a, uint32_t b0, uint32_t b1) {
    asm volatile("mma.sync.aligned.m16n8k16.row.col.f32.f16.f16.f32 "
        "{%0,%1,%2,%3}, {%4,%5,%6,%7}, {%8,%9}, {%0,%1,%2,%3};"
        : "+f"(d[0]), "+f"(d[1]), "+f"(d[2]), "+f"(d[3])
        : "r"(a[0]), "r"(a[1]), "r"(a[2]), "r"(a[3]), "r"(b0), "r"(b1));
}
__device__ __forceinline__ void cpa16(uint32_t s, const void* g) {
    asm volatile("cp.async.cg.shared.global [%0], [%1], 16;" :: "r"(s), "l"(g) : "memory");
}
#define CP_COMMIT() asm volatile("cp.async.commit_group;" ::: "memory")
#define CP_WAIT1()  asm volatile("cp.async.wait_group 1;" ::: "memory")
#define CP_WAIT0()  asm volatile("cp.async.wait_group 0;" ::: "memory")

__device__ __forceinline__ uint32_t pack2h(__half a, __half b) {
    __half2 t2 = __halves2half2(a, b);
    return *reinterpret_cast<uint32_t*>(&t2);
}

// ---------------- small utility kernels --------------------------------------
__global__ void k_copy_ns(const float* __restrict__ src) {
    int i = blockIdx.x * blockDim.x + threadIdx.x;
    if (i < BB * NN * DD) {
        float v = src[i];
        g_ns[i] = v;
        g_ns_h[i] = __float2half(v);
    }
}
__global__ void k_zero_inc() {
    int i = blockIdx.x * blockDim.x + threadIdx.x;
    if (i < BB * NN * MSG) g_inc[i] = 0.f;
}
__global__ void k_cvt_inc() {
    int i = blockIdx.x * blockDim.x + threadIdx.x;
    if (i < BB * NN * MSG) g_inc_h[i] = __float2half(g_inc[i]);
}
__global__ void k_zero_out(float* __restrict__ p, int n) {
    int i = blockIdx.x * blockDim.x + threadIdx.x;
    if (i < n) p[i] = 0.f;
}
__global__ void k_prep_w(const float* __restrict__ We1, const float* __restrict__ We2,
                         const float* __restrict__ Wn1, const float* __restrict__ Wn2) {
    int i = blockIdx.x * blockDim.x + threadIdx.x;
    const int S1 = HH * HH, S2 = S1 + MSG * HH, S3 = S2 + HH * HH, S4 = S3 + 256 * HH;
    if (i < S1) {
        int n = i >> 9, k = i & 511;
        g_We1T[i] = __float2half(We1[k * HH + n]);
    } else if (i < S2) {
        int j = i - S1; int n = j >> 9, k = j & 511;
        g_We2T[j] = __float2half(We2[k * MSG + n]);
    } else if (i < S3) {
        int j = i - S2; int n = j >> 9, k = j & 511;
        g_Wn1T[j] = __float2half(Wn1[k * HH + n]);
    } else if (i < S4) {
        int j = i - S3; int n = j >> 9, k = j & 511;
        g_Wn2T[j] = __float2half((n < UPD) ? Wn2[k * UPD + n] : 0.f);
    }
}

// ---------------- smem tile layout (XOR swizzle, 128B rows) -------------------
// region: 128 rows x 64 fp16 (128 B/row) = 16 KB; element (r, c):
//   byte = r*128 + (((c>>3) ^ (r&7)) << 4) + (c&7)*2  -> conflict-free ldmatrix
#define A_OFF 0
#define B_OFF 16384
#define BUF_SZ 32768
#define NSTAGE 3
#define SM_DYN (NSTAGE * BUF_SZ)
#define NCHUNK 8          // K = 8 * 64

__device__ __forceinline__ uint32_t swz(int r, int c0) {
    return (uint32_t)(r * 128 + ((((c0 >> 3) ^ (r & 7)) << 4)));
}

// async A tile: 128 rows x 64 fp16, row base table (element offsets)
__device__ __forceinline__ void loadA_async(uint32_t sb, const __half* __restrict__ src,
                                            const int* __restrict__ rb,
                                            int colbase, int t) {
#pragma unroll
    for (int i = 0; i < 4; ++i) {
        int f = t + i * 256;
        int row = f >> 3, seg = f & 7;
        cpa16(sb + A_OFF + swz(row, seg * 8), src + (size_t)rb[row] + colbase + seg * 8);
    }
}
// async B tile: 128 n-rows x 64 k from fp16 transposed weights [n][512]
__device__ __forceinline__ void loadB_async(uint32_t sb, const __half* __restrict__ W,
                                            int n0, int k0, int t) {
#pragma unroll
    for (int i = 0; i < 4; ++i) {
        int f = t + i * 256;
        int row = f >> 3, seg = f & 7;
        cpa16(sb + B_OFF + swz(row, seg * 8), W + (size_t)(n0 + row) * HH + k0 + seg * 8);
    }
}

// ---------------- unified fp16 HMMA GEMM kernel (3-stage cp.async) ------------
// MODE 0: edge1  relu(gather(src|snk) @ We1 + b) -> g_h16        grid(4,1024)
// MODE 1: edge2  (g_h16 @ We2 + b) scatter-atomic -> g_inc       grid(2,1024)
// MODE 2: node1  relu([inc|ns] @ Wn1 + b) -> g_h16               grid(4,256)
// MODE 3: node2  g_ns[...,2:256] += upd; refresh g_ns_h          grid(2,256)
template<int MODE>
__global__ void __launch_bounds__(256)
k_gemm(const float* __restrict__ bias,
       const int* __restrict__ esrc, const int* __restrict__ esnk) {
    extern __shared__ char sm[];
    __shared__ int tab0[128], tab1[128];
    const int t = threadIdx.x, l = t & 31, wid = t >> 5;
    const int wm = wid >> 2, wn = wid & 3;
    const int n0 = blockIdx.x * 128, r0 = blockIdx.y * 128;

    if (t < 128) {
        int r = r0 + t;
        if (MODE == 0) {
            int b = r >> 14, e = r & (EE - 1);
            tab0[t] = ((b << 12) + __ldg(esrc + e)) << 8;
            tab1[t] = ((b << 12) + __ldg(esnk + e)) << 8;
        } else if (MODE == 1) {
            int b = r >> 14, e = r & (EE - 1);
            tab0[t] = r * HH;
            tab1[t] = ((b << 12) + __ldg(esnk + e)) << 8;   // scatter dest in g_inc
        } else if (MODE == 2) {
            tab0[t] = r * DD;
        } else {
            tab0[t] = r * HH;
        }
    }
    __syncthreads();

    const __half* W;
    if (MODE == 0)      W = g_We1T;
    else if (MODE == 1) W = g_We2T;
    else if (MODE == 2) W = g_Wn1T;
    else                W = g_Wn2T;

    uint32_t smb = smem_u32(sm);

    auto issue = [&](int c) {
        uint32_t sb = smb + (c % NSTAGE) * BUF_SZ;
        const __half* a; const int* rb; int cb;
        if (MODE == 0) {
            a = g_ns_h; rb = (c < 4) ? tab0 : tab1; cb = (c & 3) * 64;
        } else if (MODE == 2) {
            a = (c < 4) ? g_inc_h : g_ns_h; rb = tab0; cb = (c & 3) * 64;
        } else {
            a = g_h16; rb = tab0; cb = c * 64;
        }
        loadA_async(sb, a, rb, cb, t);
        loadB_async(sb, W, n0, c * 64, t);
        CP_COMMIT();
    };

    float acc[4][4][4] = {};
    const int lrow8 = (((l >> 3) & 1) << 3) + (l & 7);
    const int lcol8 = (l >> 4) << 3;

    issue(0); issue(1);
    for (int c = 0; c < NCHUNK; ++c) {
        if (c < NCHUNK - 1) { CP_WAIT1(); } else { CP_WAIT0(); }
        __syncthreads();
        if (c < NCHUNK - 2) issue(c + 2);
        uint32_t sb = smb + (c % NSTAGE) * BUF_SZ;
#pragma unroll
        for (int ks = 0; ks < 4; ++ks) {
            uint32_t Af[4][4], Bf[2][4];
            const int kcol = ks * 16 + lcol8;
#pragma unroll
            for (int i = 0; i < 4; ++i)
                ldm4(Af[i], sb + A_OFF + swz(wm * 64 + i * 16 + lrow8, kcol));
#pragma unroll
            for (int g = 0; g < 2; ++g)
                ldm4(Bf[g], sb + B_OFF + swz(wn * 32 + g * 16 + lrow8, kcol));
#pragma unroll
            for (int i = 0; i < 4; ++i)
#pragma unroll
                for (int j = 0; j < 4; ++j)
                    mma_f16(acc[i][j], Af[i], Bf[j >> 1][j & 1], Bf[j >> 1][(j & 1) + 2]);
        }
    }

    // ---------------- epilogue ----------------
#pragma unroll
    for (int i = 0; i < 4; ++i) {
        const int rl = wm * 64 + i * 16 + (l >> 2);
#pragma unroll
        for (int j = 0; j < 4; ++j) {
            const int c = n0 + wn * 32 + j * 8 + ((l & 3) << 1);
            if (MODE == 0 || MODE == 2) {
                float b0 = __ldg(bias + c), b1 = __ldg(bias + c + 1);
                size_t ro0 = (size_t)(r0 + rl) * HH + c;
                size_t ro1 = (size_t)(r0 + rl + 8) * HH + c;
                float v0 = fmaxf(acc[i][j][0] + b0, 0.f);
                float v1 = fmaxf(acc[i][j][1] + b1, 0.f);
                float v2 = fmaxf(acc[i][j][2] + b0, 0.f);
                float v3 = fmaxf(acc[i][j][3] + b1, 0.f);
                *(uint32_t*)(g_h16 + ro0) = pack2h(__float2half(v0), __float2half(v1));
                *(uint32_t*)(g_h16 + ro1) = pack2h(__float2half(v2), __float2half(v3));
            } else if (MODE == 1) {
                float b0 = __ldg(bias + c), b1 = __ldg(bias + c + 1);
                int d0 = tab1[rl], d1 = tab1[rl + 8];
                atomicAdd(g_inc + d0 + c,     acc[i][j][0] + b0);
                atomicAdd(g_inc + d0 + c + 1, acc[i][j][1] + b1);
                atomicAdd(g_inc + d1 + c,     acc[i][j][2] + b0);
                atomicAdd(g_inc + d1 + c + 1, acc[i][j][3] + b1);
            } else {
                // node2: update fp32 master AND refresh fp16 shadow
                size_t ro0 = (size_t)(r0 + rl) * DD + 2;
                size_t ro1 = (size_t)(r0 + rl + 8) * DD + 2;
#pragma unroll
                for (int q = 0; q < 2; ++q) {
                    int cg = c + q;
                    if (cg < UPD) {
                        float bq = __ldg(bias + cg);
                        float nv0 = g_ns[ro0 + cg] + acc[i][j][q] + bq;
                        float nv1 = g_ns[ro1 + cg] + acc[i][j][q + 2] + bq;
                        g_ns[ro0 + cg] = nv0;
                        g_ns[ro1 + cg] = nv1;
                        g_ns_h[ro0 + cg] = __float2half(nv0);
                        g_ns_h[ro1 + cg] = __float2half(nv1);
                    }
                }
            }
        }
    }
}

// ---------------- extraction (batched attn @ ns, split-K, SIMT fp32) ----------
__global__ void __launch_bounds__(256)
k_extract(const float* __restrict__ attn, float* __restrict__ out) {
    __shared__ float As[32 * 68];
    __shared__ float Bs[32 * 128];
    int t = threadIdx.x;
    int n0 = blockIdx.x * 128;
    int kbase = blockIdx.y * 512;
    int b = blockIdx.z;
    int ty = t >> 4, tx = t & 15;
    float acc[4][8] = {};
    for (int kt = 0; kt < 16; ++kt) {
        int kabs = kbase + kt * 32;
#pragma unroll
        for (int i = 0; i < 2; ++i) {
            int f = t + i * 256;
            int row = f >> 3;
            int kq = (f & 7) << 2;
            float4 v = *(const float4*)(attn + ((size_t)(b * PP + row)) * NN + kabs + kq);
            As[(kq + 0) * 68 + row] = v.x;
            As[(kq + 1) * 68 + row] = v.y;
            As[(kq + 2) * 68 + row] = v.z;
            As[(kq + 3) * 68 + row] = v.w;
        }
#pragma unroll
        for (int i = 0; i < 4; ++i) {
            int f = t + i * 256;
            int k = f >> 5;
            int c = (f & 31) << 2;
            *(float4*)(Bs + k * 128 + c) =
                *(const float4*)(g_ns + ((size_t)(b * NN + kabs + k)) * DD + n0 + c);
        }
        __syncthreads();
#pragma unroll
        for (int k = 0; k < 32; ++k) {
            float4 a = *(const float4*)(As + k * 68 + ty * 4);
            float4 b0 = *(const float4*)(Bs + k * 128 + tx * 8);
            float4 b1 = *(const float4*)(Bs + k * 128 + tx * 8 + 4);
            float av[4] = {a.x, a.y, a.z, a.w};
            float bv[8] = {b0.x, b0.y, b0.z, b0.w, b1.x, b1.y, b1.z, b1.w};
#pragma unroll
            for (int i = 0; i < 4; ++i)
#pragma unroll
                for (int j = 0; j < 8; ++j)
                    acc[i][j] = fmaf(av[i], bv[j], acc[i][j]);
        }
        __syncthreads();
    }
#pragma unroll
    for (int i = 0; i < 4; ++i)
#pragma unroll
        for (int j = 0; j < 8; ++j)
            atomicAdd(&out[((size_t)(b * PP + ty * 4 + i)) * DD + n0 + tx * 8 + j],
                      acc[i][j]);
}

// ---------------- launcher ----------------------------------------------------
extern "C" void kernel_launch(void* const* d_in, const int* in_sizes, int n_in,
                              void* d_out, int out_size) {
    const float* nodes = (const float*)d_in[0];
    const float* attn  = (const float*)d_in[1];
    const float* We1   = (const float*)d_in[2];
    const float* be1   = (const float*)d_in[3];
    const float* We2   = (const float*)d_in[4];
    const float* be2   = (const float*)d_in[5];
    const float* Wn1   = (const float*)d_in[6];
    const float* bn1   = (const float*)d_in[7];
    const float* Wn2   = (const float*)d_in[8];
    const float* bn2   = (const float*)d_in[9];
    const int*   esrc  = (const int*)d_in[10];
    const int*   esnk  = (const int*)d_in[11];
    float* out = (float*)d_out;

    cudaFuncSetAttribute(k_gemm<0>, cudaFuncAttributeMaxDynamicSharedMemorySize, SM_DYN);
    cudaFuncSetAttribute(k_gemm<1>, cudaFuncAttributeMaxDynamicSharedMemorySize, SM_DYN);
    cudaFuncSetAttribute(k_gemm<2>, cudaFuncAttributeMaxDynamicSharedMemorySize, SM_DYN);
    cudaFuncSetAttribute(k_gemm<3>, cudaFuncAttributeMaxDynamicSharedMemorySize, SM_DYN);

    k_copy_ns<<<(BB * NN * DD + 1023) / 1024, 1024>>>(nodes);
    k_prep_w<<<(2 * HH * HH + 2 * 256 * HH + 255) / 256, 256>>>(We1, We2, Wn1, Wn2);

    for (int s = 0; s < STEPS; ++s) {
        k_zero_inc<<<(BB * NN * MSG + 1023) / 1024, 1024>>>();
        k_gemm<0><<<dim3(4, (BB * EE) / 128), 256, SM_DYN>>>(be1, esrc, esnk);
        k_gemm<1><<<dim3(2, (BB * EE) / 128), 256, SM_DYN>>>(be2, esrc, esnk);
        k_cvt_inc<<<(BB * NN * MSG + 1023) / 1024, 1024>>>();
        k_gemm<2><<<dim3(4, (BB * NN) / 128), 256, SM_DYN>>>(bn1, esrc, esnk);
        k_gemm<3><<<dim3(2, (BB * NN) / 128), 256, SM_DYN>>>(bn2, esrc, esnk);
    }

    k_zero_out<<<(out_size + 255) / 256, 256>>>(out, out_size);
    k_extract<<<dim3(2, 8, 8), 256>>>(attn, out);
}